// round 16
// baseline (speedup 1.0000x reference)
#include <cuda_runtime.h>
#include <cuda_fp16.h>
#include <cstdint>
#include <cstddef>

#define B 32
#define L 128
#define D 256
#define T 10000
#define TN 64          // t-tile per CTA
#define NTILES 157     // ceil(10000/64)
#define SA 40          // smem row stride in halves (80B, conflict-free ldmatrix)

// ---------------- device scratch ----------------
__device__ float g_dm[B * D];
__device__ float g_q[4 * B * T];
__device__ float g_item[B * T];
__device__ float g_norm2[5 * B];
__device__ __half g_w5h[T * D];
__device__ __half g_embh[(T + 1) * D];

// ---------------- helpers ----------------
__device__ __forceinline__ float fast_tanh(float x) {
    float y;
    asm("tanh.approx.f32 %0, %1;" : "=f"(y) : "f"(x));
    return y;
}

__device__ __forceinline__ uint32_t smem_u32(const void* p) {
    uint32_t a;
    asm("{ .reg .u64 t; cvta.to.shared.u64 t, %1; cvt.u32.u64 %0, t; }" : "=r"(a) : "l"(p));
    return a;
}

__device__ __forceinline__ void ldm_x4(uint32_t* f, uint32_t addr) {
    asm volatile("ldmatrix.sync.aligned.m8n8.x4.shared.b16 {%0,%1,%2,%3}, [%4];"
                 : "=r"(f[0]), "=r"(f[1]), "=r"(f[2]), "=r"(f[3]) : "r"(addr));
}

__device__ __forceinline__ void mma16816(float* c, const uint32_t* a, const uint32_t* b) {
    asm volatile(
        "mma.sync.aligned.m16n8k16.row.col.f32.f16.f16.f32 "
        "{%0,%1,%2,%3},{%4,%5,%6,%7},{%8,%9},{%0,%1,%2,%3};"
        : "+f"(c[0]), "+f"(c[1]), "+f"(c[2]), "+f"(c[3])
        : "r"(a[0]), "r"(a[1]), "r"(a[2]), "r"(a[3]), "r"(b[0]), "r"(b[1]));
}

__device__ __forceinline__ void cp16(uint32_t dst, const void* src) {
    asm volatile("cp.async.cg.shared.global [%0], [%1], 16;" :: "r"(dst), "l"(src));
}

__device__ __forceinline__ void cp16z(uint32_t dst, const void* src, uint32_t bytes) {
    asm volatile("cp.async.cg.shared.global [%0], [%1], 16, %2;" :: "r"(dst), "l"(src), "r"(bytes));
}

// ---------------- main stream: fp16 tables + item-norm zero ----------------
__global__ void cvt_kernel(const float* __restrict__ w5, const float* __restrict__ emb) {
    const int idx = blockIdx.x * 256 + threadIdx.x;
    const int i4 = idx * 4;
    if (i4 < T * D) {
        const float4 w = __ldg((const float4*)(w5 + i4));
        __half2* dst = (__half2*)(g_w5h + i4);
        dst[0] = __floats2half2_rn(w.x, w.y);
        dst[1] = __floats2half2_rn(w.z, w.w);
    }
    if (i4 < (T + 1) * D) {
        const float4 x = __ldg((const float4*)(emb + i4));
        ((__half2*)(g_embh + i4))[0] = __floats2half2_rn(x.x, x.y);
        ((__half2*)(g_embh + i4))[1] = __floats2half2_rn(x.z, x.w);
    }
    if (blockIdx.x == 0 && threadIdx.x < B) g_norm2[4 * B + threadIdx.x] = 0.f;
}

// ---------------- side stream: dm + q-norm zero + tgt fill ----------------
__global__ void dm_kernel(const float* __restrict__ data, float* __restrict__ tgt) {
    const int b = blockIdx.x;
    const int d = threadIdx.x;
    if (b == 0 && d < 4 * B) g_norm2[d] = 0.f;
    const float* p = data + (size_t)b * L * D + d;
    float s = 0.f;
#pragma unroll 8
    for (int l = 0; l < L; ++l) s += p[(size_t)l * D];
    g_dm[b * D + d] = s * (1.0f / (float)L);
    // fill target with ones (grid-stride over B*T)
    for (int i = b * 256 + d; i < B * T; i += B * 256) tgt[i] = 1.f;
}

// ---------------- side stream: q GEMMs (+ norm partials, + tgt scatter) ----------------
__global__ void q_kernel(const float* __restrict__ W1, const float* __restrict__ W2,
                         const float* __restrict__ W3, const float* __restrict__ W4,
                         const int* __restrict__ event_type, float* __restrict__ tgt) {
    __shared__ float dmt[D][B];
    __shared__ float qs[8][32];
    const int tid = threadIdx.x;

    if (blockIdx.x == 0 && blockIdx.y == 0) {
        for (int i = tid; i < B * L; i += 256) {
            const int e = event_type[i];
            if (e != 0) tgt[(size_t)(i >> 7) * T + (e - 1)] = 0.f;
        }
    }

    for (int i = tid; i < B * D; i += 256) {
        int b = i >> 8;
        int d = i & 255;
        dmt[d][b] = g_dm[i];
    }
    __syncthreads();

    const float* W = (blockIdx.y == 0) ? W1 : (blockIdx.y == 1) ? W2
                   : (blockIdx.y == 2) ? W3 : W4;
    float* q = g_q + (size_t)blockIdx.y * B * T;

    const int warp = tid >> 5;
    const int lane = tid & 31;
    const int t0 = blockIdx.x * 128 + warp * 16;

    float sq = 0.f;
    for (int it = 0; it < 16; ++it) {
        const int t = t0 + it;
        if (t >= T) break;
        const float4* wr = (const float4*)(W + (size_t)t * D);
        float s = 0.f;
#pragma unroll
        for (int k4 = 0; k4 < D / 4; ++k4) {
            float4 w4 = __ldg(&wr[k4]);
            const int d = k4 * 4;
            s += w4.x * dmt[d + 0][lane];
            s += w4.y * dmt[d + 1][lane];
            s += w4.z * dmt[d + 2][lane];
            s += w4.w * dmt[d + 3][lane];
        }
        q[(size_t)lane * T + t] = s;
        sq += s * s;
    }
    qs[warp][lane] = sq;
    __syncthreads();
    if (tid < 32) {
        float tot = 0.f;
#pragma unroll
        for (int w = 0; w < 8; ++w) tot += qs[w][tid];
        atomicAdd(&g_norm2[blockIdx.y * B + tid], tot);
    }
}

// ---------------- main fused HMMA kernel (3-stage, 1 barrier/chunk, 3 CTAs/SM) ----------------
#define STG     15360                 // A 10240 | B 5120
#define OF_A    0
#define OF_B    10240
#define SM_EID  (3 * STG)             // 46080
#define SM_RED  (SM_EID + 512)
#define SM_BYTES (SM_RED + 4 * TN * 4)

__global__ __launch_bounds__(256, 3)
void item_kernel(const int* __restrict__ event_type,
                 const float* __restrict__ corr,
                 const float* __restrict__ drop) {
    extern __shared__ char smem[];
    const uint32_t sb = smem_u32(smem);
    int* sEid = (int*)(smem + SM_EID);
    float (*red)[TN] = (float (*)[TN])(smem + SM_RED);

    const int tid  = threadIdx.x;
    const int warp = tid >> 5;
    const int lane = tid & 31;
    const int wm   = warp & 3;
    const int wn   = warp >> 2;
    const int b     = blockIdx.y;
    const int tBase = blockIdx.x * TN;
    const bool tfull = (tBase + TN <= T);

    if (tid < L) sEid[tid] = event_type[b * L + tid];
    __syncthreads();

    const int arow = tid >> 1;
    const int ah   = tid & 1;
    const int eidA = sEid[arow];
    const char* gA = (const char*)(g_embh + (size_t)eidA * D);
    const int brow = tid >> 2;
    const int bq   = tid & 3;
    const int trow = tBase + brow;
    const bool tOk = trow < T;
    const char* gB = (const char*)(g_w5h + (size_t)(tOk ? trow : 0) * D);
    const uint32_t bbytes = tOk ? 16u : 0u;

    const uint32_t dA = arow * 80 + ah * 32;
    const uint32_t dB = brow * 80 + bq * 16;

    auto issue = [&](int c, int st) {
        const int go = c * 64;
        const uint32_t s0 = sb + (uint32_t)st * STG;
        cp16(s0 + OF_A + dA,      gA + go + ah * 32);
        cp16(s0 + OF_A + dA + 16, gA + go + ah * 32 + 16);
        cp16z(s0 + OF_B + dB, gB + go + bq * 16, bbytes);
        asm volatile("cp.async.commit_group;" ::: "memory");
    };

    float acc[2][4][4];
#pragma unroll
    for (int i = 0; i < 2; ++i)
#pragma unroll
        for (int j = 0; j < 4; ++j)
#pragma unroll
            for (int r = 0; r < 4; ++r) acc[i][j][r] = 0.f;

    const int arow_base = wm * 32 + ((lane >> 3) & 1) * 8 + (lane & 7);
    const int acol_sub  = (lane >> 4) * 8;
    const int brow_base = wn * 32 + ((lane >> 4) & 1) * 8 + (lane & 7);
    const int bcol_sub  = ((lane >> 3) & 1) * 8;

    issue(0, 0);
    issue(1, 1);

#pragma unroll 1
    for (int c = 0; c < 8; ++c) {
        const int st = c % 3;
        if (c < 7) {
            asm volatile("cp.async.wait_group 1;" ::: "memory");
        } else {
            asm volatile("cp.async.wait_group 0;" ::: "memory");
        }
        __syncthreads();                 // stage c ready; all warps done with stage c-1
        if (c < 6) issue(c + 2, (c + 2) % 3);

        const uint32_t s0 = sb + (uint32_t)st * STG;
        const uint32_t aA = s0 + OF_A;
        const uint32_t aB = s0 + OF_B;

#pragma unroll
        for (int kk = 0; kk < 2; ++kk) {
            uint32_t af[2][4], bf[4][2];
#pragma unroll
            for (int i = 0; i < 2; ++i) {
                const uint32_t off = (uint32_t)((arow_base + i * 16) * SA + kk * 16 + acol_sub) * 2;
                ldm_x4(af[i], aA + off);
            }
#pragma unroll
            for (int jp = 0; jp < 2; ++jp) {
                const uint32_t off = (uint32_t)((brow_base + jp * 16) * SA + kk * 16 + bcol_sub) * 2;
                ldm_x4(&bf[jp * 2][0], aB + off);
            }
#pragma unroll
            for (int i = 0; i < 2; ++i)
#pragma unroll
                for (int j = 0; j < 4; ++j)
                    mma16816(acc[i][j], af[i], bf[j]);
        }
    }
    __syncthreads();

    // ---- fused epilogue ----
    float pcol[8];
#pragma unroll
    for (int k = 0; k < 8; ++k) pcol[k] = 0.f;

#pragma unroll
    for (int i = 0; i < 2; ++i) {
#pragma unroll
        for (int p = 0; p < 2; ++p) {
            const int r = wm * 32 + i * 16 + p * 8 + (lane >> 2);
            const int e = sEid[r];
            const float* dr = drop + ((size_t)(b * L + r)) * T;
            const float* cr = corr + (size_t)(e - 1) * T;
#pragma unroll
            for (int j = 0; j < 4; ++j) {
                const int col = tBase + wn * 32 + j * 8 + (lane & 3) * 2;
                if (e > 0 && (tfull || col < T)) {
                    const float2 d2 = __ldg((const float2*)(dr + col));
                    const float2 c2 = __ldg((const float2*)(cr + col));
                    pcol[j * 2 + 0] += fast_tanh(acc[i][j][p * 2 + 0]) * d2.x * c2.x;
                    pcol[j * 2 + 1] += fast_tanh(acc[i][j][p * 2 + 1]) * d2.y * c2.y;
                }
            }
        }
    }

#pragma unroll
    for (int mask = 4; mask <= 16; mask <<= 1)
#pragma unroll
        for (int k = 0; k < 8; ++k)
            pcol[k] += __shfl_xor_sync(0xffffffffu, pcol[k], mask);

    if (lane < 4) {
#pragma unroll
        for (int j = 0; j < 4; ++j) {
            red[wm][wn * 32 + j * 8 + lane * 2 + 0] = pcol[j * 2 + 0];
            red[wm][wn * 32 + j * 8 + lane * 2 + 1] = pcol[j * 2 + 1];
        }
    }
    __syncthreads();

    if (tid < TN) {
        const int t = tBase + tid;
        float s = 0.f;
        if (t < T) {
            s = red[0][tid] + red[1][tid] + red[2][tid] + red[3][tid];
            g_item[(size_t)b * T + t] = s;
        }
        float sq = s * s;
#pragma unroll
        for (int o = 16; o; o >>= 1) sq += __shfl_xor_sync(0xffffffffu, sq, o);
        if (lane == 0) atomicAdd(&g_norm2[4 * B + b], sq);
    }
}

// ---------------- final combine ----------------
__global__ void final_kernel(const float* __restrict__ pa, const float* __restrict__ pb,
                             const float* __restrict__ pc, const float* __restrict__ pd,
                             float* __restrict__ out) {
    const int b = blockIdx.y;
    const int t = blockIdx.x * 256 + threadIdx.x;
    if (t >= T) return;
    auto inv = [](float n2) { return (n2 > 1e-10f) ? rsqrtf(n2) : 1e5f; };
    const float i0 = inv(g_norm2[0 * B + b]);
    const float i1 = inv(g_norm2[1 * B + b]);
    const float i2 = inv(g_norm2[2 * B + b]);
    const float i3 = inv(g_norm2[3 * B + b]);
    const float i4 = inv(g_norm2[4 * B + b]);
    const float ca = pa[0], cb = pb[0], cc = pc[0], cd = pd[0];
    float s = g_q[0 * B * T + (size_t)b * T + t] * i0 * ca
            + g_q[1 * B * T + (size_t)b * T + t] * i1 * cb
            + g_q[2 * B * T + (size_t)b * T + t] * i2 * cc
            + g_q[3 * B * T + (size_t)b * T + t] * i3 * cd
            + g_item[(size_t)b * T + t] * i4;
    out[(size_t)b * T + t] = tanhf(s);
}

// ---------------- launch: two fully parallel chains ----------------
// main: cvt(tables) -> item      side: dm(+fill) -> q(+scatter)
extern "C" void kernel_launch(void* const* d_in, const int* in_sizes, int n_in,
                              void* d_out, int out_size) {
    const float* data = (const float*)d_in[0];
    const int*   ev   = (const int*)d_in[1];
    const float* emb  = (const float*)d_in[2];
    const float* corr = (const float*)d_in[3];
    const float* W1   = (const float*)d_in[4];
    const float* W2   = (const float*)d_in[5];
    const float* W3   = (const float*)d_in[6];
    const float* W4   = (const float*)d_in[7];
    const float* W5   = (const float*)d_in[8];
    const float* a    = (const float*)d_in[9];
    const float* bb   = (const float*)d_in[10];
    const float* c    = (const float*)d_in[11];
    const float* dd   = (const float*)d_in[12];
    const float* drop = (const float*)d_in[13];

    float* out = (float*)d_out;
    float* tgt = out + B * T;

    cudaFuncSetAttribute(item_kernel, cudaFuncAttributeMaxDynamicSharedMemorySize, SM_BYTES);

    cudaStream_t side;
    cudaEvent_t evFork, evJoin;
    cudaStreamCreateWithFlags(&side, cudaStreamNonBlocking);   // leaked (few calls total)
    cudaEventCreateWithFlags(&evFork, cudaEventDisableTiming);
    cudaEventCreateWithFlags(&evJoin, cudaEventDisableTiming);

    // fork at origin
    cudaEventRecord(evFork, 0);
    cudaStreamWaitEvent(side, evFork, 0);

    // side chain: dm (+tgt fill, q-norm zero) -> q (+scatter, q-norm partials)
    dm_kernel<<<B, 256, 0, side>>>(data, tgt);
    q_kernel<<<dim3((T + 127) / 128, 4), 256, 0, side>>>(W1, W2, W3, W4, ev, tgt);
    cudaEventRecord(evJoin, side);

    // main chain: cvt (tables, item-norm zero) -> item
    const int cvtBlocks = (((T + 1) * D) / 4 + 255) / 256;   // 2501
    cvt_kernel<<<cvtBlocks, 256>>>(W5, emb);
    item_kernel<<<dim3(NTILES, B), 256, SM_BYTES>>>(ev, corr, drop);

    cudaStreamWaitEvent(0, evJoin, 0);
    final_kernel<<<dim3((T + 255) / 256, B), 256>>>(a, bb, c, dd, out);
}

// round 17
// speedup vs baseline: 1.5809x; 1.5809x over previous
#include <cuda_runtime.h>
#include <cuda_fp16.h>
#include <cstdint>
#include <cstddef>

#define B 32
#define L 128
#define D 256
#define T 10000
#define TN 64          // t-tile per CTA
#define NTILES 157     // ceil(10000/64)
#define SA 40          // smem row stride in halves (80B, conflict-free ldmatrix)

// ---------------- device scratch ----------------
__device__ float g_dm[B * D];
__device__ float g_q[4 * B * T];
__device__ float g_item[B * T];
__device__ float g_norm2[5 * B];
__device__ __half g_w5h[T * D];
__device__ __half g_embh[(T + 1) * D];

// ---------------- helpers ----------------
__device__ __forceinline__ float fast_tanh(float x) {
    float y;
    asm("tanh.approx.f32 %0, %1;" : "=f"(y) : "f"(x));
    return y;
}

__device__ __forceinline__ uint32_t smem_u32(const void* p) {
    uint32_t a;
    asm("{ .reg .u64 t; cvta.to.shared.u64 t, %1; cvt.u32.u64 %0, t; }" : "=r"(a) : "l"(p));
    return a;
}

__device__ __forceinline__ void ldm_x4(uint32_t* f, uint32_t addr) {
    asm volatile("ldmatrix.sync.aligned.m8n8.x4.shared.b16 {%0,%1,%2,%3}, [%4];"
                 : "=r"(f[0]), "=r"(f[1]), "=r"(f[2]), "=r"(f[3]) : "r"(addr));
}

__device__ __forceinline__ void mma16816(float* c, const uint32_t* a, const uint32_t* b) {
    asm volatile(
        "mma.sync.aligned.m16n8k16.row.col.f32.f16.f16.f32 "
        "{%0,%1,%2,%3},{%4,%5,%6,%7},{%8,%9},{%0,%1,%2,%3};"
        : "+f"(c[0]), "+f"(c[1]), "+f"(c[2]), "+f"(c[3])
        : "r"(a[0]), "r"(a[1]), "r"(a[2]), "r"(a[3]), "r"(b[0]), "r"(b[1]));
}

__device__ __forceinline__ void cp16(uint32_t dst, const void* src) {
    asm volatile("cp.async.cg.shared.global [%0], [%1], 16;" :: "r"(dst), "l"(src));
}

__device__ __forceinline__ void cp16z(uint32_t dst, const void* src, uint32_t bytes) {
    asm volatile("cp.async.cg.shared.global [%0], [%1], 16, %2;" :: "r"(dst), "l"(src), "r"(bytes));
}

// ---------------- precompute tables + dm + zero norms + tgt fill (R10 layout) ----------------
__global__ void cvt_kernel(const float* __restrict__ w5, const float* __restrict__ emb,
                           const float* __restrict__ data, float* __restrict__ tgt) {
    const int idx = blockIdx.x * 256 + threadIdx.x;
    const int i4 = idx * 4;
    if (i4 < T * D) {
        const float4 w = __ldg((const float4*)(w5 + i4));
        __half2* dst = (__half2*)(g_w5h + i4);
        dst[0] = __floats2half2_rn(w.x, w.y);
        dst[1] = __floats2half2_rn(w.z, w.w);
    }
    if (i4 < (T + 1) * D) {
        const float4 x = __ldg((const float4*)(emb + i4));
        ((__half2*)(g_embh + i4))[0] = __floats2half2_rn(x.x, x.y);
        ((__half2*)(g_embh + i4))[1] = __floats2half2_rn(x.z, x.w);
    }
    if (idx < B * T) tgt[idx] = 1.f;
    if (blockIdx.x < B) {
        const int b = blockIdx.x;
        const int d = threadIdx.x;
        if (b == 0 && d < 5 * B) g_norm2[d] = 0.f;
        const float* p = data + (size_t)b * L * D + d;
        float s = 0.f;
#pragma unroll 8
        for (int l = 0; l < L; ++l) s += p[(size_t)l * D];
        g_dm[b * D + d] = s * (1.0f / (float)L);
    }
}

// ---------------- q[w][b,t] = dm[b,:] . W_w[t,:]  (+ norm partials, + tgt scatter) ----------------
__global__ void q_kernel(const float* __restrict__ W1, const float* __restrict__ W2,
                         const float* __restrict__ W3, const float* __restrict__ W4,
                         const int* __restrict__ event_type, float* __restrict__ tgt) {
    __shared__ float dmt[D][B];
    __shared__ float qs[8][32];
    const int tid = threadIdx.x;

    // folded target scatter (after cvt's fill, guaranteed by stream order)
    if (blockIdx.x == 0 && blockIdx.y == 0) {
        for (int i = tid; i < B * L; i += 256) {
            const int e = event_type[i];
            if (e != 0) tgt[(size_t)(i >> 7) * T + (e - 1)] = 0.f;
        }
    }

    for (int i = tid; i < B * D; i += 256) {
        int b = i >> 8;
        int d = i & 255;
        dmt[d][b] = g_dm[i];
    }
    __syncthreads();

    const float* W = (blockIdx.y == 0) ? W1 : (blockIdx.y == 1) ? W2
                   : (blockIdx.y == 2) ? W3 : W4;
    float* q = g_q + (size_t)blockIdx.y * B * T;

    const int warp = tid >> 5;
    const int lane = tid & 31;
    const int t0 = blockIdx.x * 128 + warp * 16;

    float sq = 0.f;
    for (int it = 0; it < 16; ++it) {
        const int t = t0 + it;
        if (t >= T) break;
        const float4* wr = (const float4*)(W + (size_t)t * D);
        float s = 0.f;
#pragma unroll
        for (int k4 = 0; k4 < D / 4; ++k4) {
            float4 w4 = __ldg(&wr[k4]);
            const int d = k4 * 4;
            s += w4.x * dmt[d + 0][lane];
            s += w4.y * dmt[d + 1][lane];
            s += w4.z * dmt[d + 2][lane];
            s += w4.w * dmt[d + 3][lane];
        }
        q[(size_t)lane * T + t] = s;
        sq += s * s;
    }
    qs[warp][lane] = sq;
    __syncthreads();
    if (tid < 32) {
        float tot = 0.f;
#pragma unroll
        for (int w = 0; w < 8; ++w) tot += qs[w][tid];
        atomicAdd(&g_norm2[blockIdx.y * B + tid], tot);
    }
}

// ---------------- main fused HMMA kernel (3-stage, 1 barrier/chunk, 3 CTAs/SM) ----------------
#define STG     15360                 // A 10240 | B 5120
#define OF_A    0
#define OF_B    10240
#define SM_EID  (3 * STG)             // 46080
#define SM_RED  (SM_EID + 512)
#define SM_BYTES (SM_RED + 4 * TN * 4)

__global__ __launch_bounds__(256, 3)
void item_kernel(const int* __restrict__ event_type,
                 const float* __restrict__ corr,
                 const float* __restrict__ drop) {
    extern __shared__ char smem[];
    const uint32_t sb = smem_u32(smem);
    int* sEid = (int*)(smem + SM_EID);
    float (*red)[TN] = (float (*)[TN])(smem + SM_RED);

    const int tid  = threadIdx.x;
    const int warp = tid >> 5;
    const int lane = tid & 31;
    const int wm   = warp & 3;
    const int wn   = warp >> 2;
    const int b     = blockIdx.y;
    const int tBase = blockIdx.x * TN;
    const bool tfull = (tBase + TN <= T);

    if (tid < L) sEid[tid] = event_type[b * L + tid];
    __syncthreads();

    const int arow = tid >> 1;
    const int ah   = tid & 1;
    const int eidA = sEid[arow];
    const char* gA = (const char*)(g_embh + (size_t)eidA * D);
    const int brow = tid >> 2;
    const int bq   = tid & 3;
    const int trow = tBase + brow;
    const bool tOk = trow < T;
    const char* gB = (const char*)(g_w5h + (size_t)(tOk ? trow : 0) * D);
    const uint32_t bbytes = tOk ? 16u : 0u;

    const uint32_t dA = arow * 80 + ah * 32;
    const uint32_t dB = brow * 80 + bq * 16;

    auto issue = [&](int c, int st) {
        const int go = c * 64;
        const uint32_t s0 = sb + (uint32_t)st * STG;
        cp16(s0 + OF_A + dA,      gA + go + ah * 32);
        cp16(s0 + OF_A + dA + 16, gA + go + ah * 32 + 16);
        cp16z(s0 + OF_B + dB, gB + go + bq * 16, bbytes);
        asm volatile("cp.async.commit_group;" ::: "memory");
    };

    float acc[2][4][4];
#pragma unroll
    for (int i = 0; i < 2; ++i)
#pragma unroll
        for (int j = 0; j < 4; ++j)
#pragma unroll
            for (int r = 0; r < 4; ++r) acc[i][j][r] = 0.f;

    const int arow_base = wm * 32 + ((lane >> 3) & 1) * 8 + (lane & 7);
    const int acol_sub  = (lane >> 4) * 8;
    const int brow_base = wn * 32 + ((lane >> 4) & 1) * 8 + (lane & 7);
    const int bcol_sub  = ((lane >> 3) & 1) * 8;

    issue(0, 0);
    issue(1, 1);

#pragma unroll 1
    for (int c = 0; c < 8; ++c) {
        const int st = c % 3;
        if (c < 7) {
            asm volatile("cp.async.wait_group 1;" ::: "memory");
        } else {
            asm volatile("cp.async.wait_group 0;" ::: "memory");
        }
        __syncthreads();                 // stage c ready; all warps done with stage c-1
        if (c < 6) issue(c + 2, (c + 2) % 3);

        const uint32_t s0 = sb + (uint32_t)st * STG;
        const uint32_t aA = s0 + OF_A;
        const uint32_t aB = s0 + OF_B;

#pragma unroll
        for (int kk = 0; kk < 2; ++kk) {
            uint32_t af[2][4], bf[4][2];
#pragma unroll
            for (int i = 0; i < 2; ++i) {
                const uint32_t off = (uint32_t)((arow_base + i * 16) * SA + kk * 16 + acol_sub) * 2;
                ldm_x4(af[i], aA + off);
            }
#pragma unroll
            for (int jp = 0; jp < 2; ++jp) {
                const uint32_t off = (uint32_t)((brow_base + jp * 16) * SA + kk * 16 + bcol_sub) * 2;
                ldm_x4(&bf[jp * 2][0], aB + off);
            }
#pragma unroll
            for (int i = 0; i < 2; ++i)
#pragma unroll
                for (int j = 0; j < 4; ++j)
                    mma16816(acc[i][j], af[i], bf[j]);
        }
    }
    __syncthreads();

    // ---- fused epilogue ----
    float pcol[8];
#pragma unroll
    for (int k = 0; k < 8; ++k) pcol[k] = 0.f;

#pragma unroll
    for (int i = 0; i < 2; ++i) {
#pragma unroll
        for (int p = 0; p < 2; ++p) {
            const int r = wm * 32 + i * 16 + p * 8 + (lane >> 2);
            const int e = sEid[r];
            const float* dr = drop + ((size_t)(b * L + r)) * T;
            const float* cr = corr + (size_t)(e - 1) * T;
#pragma unroll
            for (int j = 0; j < 4; ++j) {
                const int col = tBase + wn * 32 + j * 8 + (lane & 3) * 2;
                if (e > 0 && (tfull || col < T)) {
                    const float2 d2 = __ldg((const float2*)(dr + col));
                    const float2 c2 = __ldg((const float2*)(cr + col));
                    pcol[j * 2 + 0] += fast_tanh(acc[i][j][p * 2 + 0]) * d2.x * c2.x;
                    pcol[j * 2 + 1] += fast_tanh(acc[i][j][p * 2 + 1]) * d2.y * c2.y;
                }
            }
        }
    }

#pragma unroll
    for (int mask = 4; mask <= 16; mask <<= 1)
#pragma unroll
        for (int k = 0; k < 8; ++k)
            pcol[k] += __shfl_xor_sync(0xffffffffu, pcol[k], mask);

    if (lane < 4) {
#pragma unroll
        for (int j = 0; j < 4; ++j) {
            red[wm][wn * 32 + j * 8 + lane * 2 + 0] = pcol[j * 2 + 0];
            red[wm][wn * 32 + j * 8 + lane * 2 + 1] = pcol[j * 2 + 1];
        }
    }
    __syncthreads();

    if (tid < TN) {
        const int t = tBase + tid;
        float s = 0.f;
        if (t < T) {
            s = red[0][tid] + red[1][tid] + red[2][tid] + red[3][tid];
            g_item[(size_t)b * T + t] = s;
        }
        float sq = s * s;
#pragma unroll
        for (int o = 16; o; o >>= 1) sq += __shfl_xor_sync(0xffffffffu, sq, o);
        if (lane == 0) atomicAdd(&g_norm2[4 * B + b], sq);
    }
}

// ---------------- final combine ----------------
__global__ void final_kernel(const float* __restrict__ pa, const float* __restrict__ pb,
                             const float* __restrict__ pc, const float* __restrict__ pd,
                             float* __restrict__ out) {
    const int b = blockIdx.y;
    const int t = blockIdx.x * 256 + threadIdx.x;
    if (t >= T) return;
    auto inv = [](float n2) { return (n2 > 1e-10f) ? rsqrtf(n2) : 1e5f; };
    const float i0 = inv(g_norm2[0 * B + b]);
    const float i1 = inv(g_norm2[1 * B + b]);
    const float i2 = inv(g_norm2[2 * B + b]);
    const float i3 = inv(g_norm2[3 * B + b]);
    const float i4 = inv(g_norm2[4 * B + b]);
    const float ca = pa[0], cb = pb[0], cc = pc[0], cd = pd[0];
    float s = g_q[0 * B * T + (size_t)b * T + t] * i0 * ca
            + g_q[1 * B * T + (size_t)b * T + t] * i1 * cb
            + g_q[2 * B * T + (size_t)b * T + t] * i2 * cc
            + g_q[3 * B * T + (size_t)b * T + t] * i3 * cd
            + g_item[(size_t)b * T + t] * i4;
    out[(size_t)b * T + t] = tanhf(s);
}

// ---------------- launch (R10 fork topology: fork AFTER cvt) ----------------
extern "C" void kernel_launch(void* const* d_in, const int* in_sizes, int n_in,
                              void* d_out, int out_size) {
    const float* data = (const float*)d_in[0];
    const int*   ev   = (const int*)d_in[1];
    const float* emb  = (const float*)d_in[2];
    const float* corr = (const float*)d_in[3];
    const float* W1   = (const float*)d_in[4];
    const float* W2   = (const float*)d_in[5];
    const float* W3   = (const float*)d_in[6];
    const float* W4   = (const float*)d_in[7];
    const float* W5   = (const float*)d_in[8];
    const float* a    = (const float*)d_in[9];
    const float* bb   = (const float*)d_in[10];
    const float* c    = (const float*)d_in[11];
    const float* dd   = (const float*)d_in[12];
    const float* drop = (const float*)d_in[13];

    float* out = (float*)d_out;
    float* tgt = out + B * T;

    cudaFuncSetAttribute(item_kernel, cudaFuncAttributeMaxDynamicSharedMemorySize, SM_BYTES);

    cudaStream_t side;
    cudaEvent_t evFork, evJoin;
    cudaStreamCreateWithFlags(&side, cudaStreamNonBlocking);   // leaked (few calls total)
    cudaEventCreateWithFlags(&evFork, cudaEventDisableTiming);
    cudaEventCreateWithFlags(&evJoin, cudaEventDisableTiming);

    const int cvtBlocks = (((T + 1) * D) / 4 + 255) / 256;   // 2501
    cvt_kernel<<<cvtBlocks, 256>>>(W5, emb, data, tgt);

    cudaEventRecord(evFork, 0);
    cudaStreamWaitEvent(side, evFork, 0);

    // side: q (+ scatter) concurrent with item on the default stream
    q_kernel<<<dim3((T + 127) / 128, 4), 256, 0, side>>>(W1, W2, W3, W4, ev, tgt);
    cudaEventRecord(evJoin, side);

    item_kernel<<<dim3(NTILES, B), 256, SM_BYTES>>>(ev, corr, drop);

    cudaStreamWaitEvent(0, evJoin, 0);
    final_kernel<<<dim3((T + 255) / 256, B), 256>>>(a, bb, c, dd, out);
}